// round 1
// baseline (speedup 1.0000x reference)
#include <cuda_runtime.h>
#include <cstdint>
#include <cstddef>

#define BATCHN 8
#define DMODEL 192
#define DINNER 384
#define DSTATE 16
#define DTRANK 12
#define HHN 48
#define LLN 2304            // 48*48
#define M_TOT (BATCHN*LLN)  // 18432
#define NXP 44              // DTRANK + 2*DSTATE
#define EPSF 1e-5f

// ---------------- scratch (no allocations allowed) ----------------
__device__ float  g_xz   [(size_t)M_TOT*768];     // in_proj output: [m][768] (xin | z)
__device__ float  g_xact [(size_t)M_TOT*DINNER];  // conv+silu output (B,L,D)
__device__ float  g_xp   [(size_t)M_TOT*NXP];     // x_proj output
__device__ float2 g_dd   [(size_t)M_TOT*DINNER];  // (delta, delta*u)
__device__ float4 g_bc   [(size_t)M_TOT*8];       // (B[2s],C[2s],B[2s+1],C[2s+1])
__device__ float  g_y    [(size_t)M_TOT*DINNER];  // scan output (without u*D)
__device__ float  g_gate [(size_t)M_TOT*DINNER];  // LN * silu(z)
__device__ float  g_fused[(size_t)M_TOT*DMODEL];  // combined out_proj+fuse GEMM
__device__ float  g_Wc   [DMODEL*DINNER];         // fuse_w @ out_proj_w
__device__ float  g_dtwT [DTRANK*DINNER];         // dt_proj_w transposed [r][d]
__device__ float  g_wT   [9*DINNER];              // conv_w transposed [j][d]
__device__ float2 g_stat [BATCHN*DMODEL];         // instance-norm (mean, rstd)

// ---------------- prep: Wc = fuse_w @ out_proj_w ; transposes ----------------
__global__ void prep_kernel(const float* __restrict__ fuse_w,
                            const float* __restrict__ out_proj_w,
                            const float* __restrict__ dt_proj_w,
                            const float* __restrict__ conv_w)
{
    int gid = blockIdx.x * blockDim.x + threadIdx.x;
    if (gid < DMODEL * DINNER) {
        int c = gid / DINNER, d = gid % DINNER;
        float s = 0.f;
        for (int o = 0; o < DMODEL; o++)
            s += fuse_w[c * DMODEL + o] * out_proj_w[(size_t)o * DINNER + d];
        g_Wc[gid] = s;
    } else if (gid < DMODEL * DINNER + DTRANK * DINNER) {
        int t = gid - DMODEL * DINNER;
        int r = t / DINNER, d = t % DINNER;
        g_dtwT[t] = dt_proj_w[d * DTRANK + r];
    } else if (gid < DMODEL * DINNER + DTRANK * DINNER + 9 * DINNER) {
        int t = gid - DMODEL * DINNER - DTRANK * DINNER;
        int j = t / DINNER, d = t % DINNER;
        g_wT[t] = conv_w[d * 9 + j];
    }
}

// ---------------- generic tiled SGEMM: C[m][n] = sum_k A.. * W[n][k] ----------------
// TRANSA=0: A row-major [M,K]. TRANSA=1: A[m][k] = A[(b*K+k)*LLN + l], b=m/LLN, l=m%LLN.
template<int TRANSA>
__global__ void __launch_bounds__(256) sgemm_kernel(
    const float* __restrict__ A, const float* __restrict__ W,
    const float* __restrict__ bias, float* __restrict__ C,
    int M, int N, int K)
{
    __shared__ float As[16 * 64];
    __shared__ float Bs[16 * 64];
    const int tid = threadIdx.x;
    const int tx = tid & 15;
    const int ty = tid >> 4;
    const int m0 = blockIdx.y * 64;
    const int n0 = blockIdx.x * 64;

    float acc[4][4];
#pragma unroll
    for (int i = 0; i < 4; i++)
#pragma unroll
        for (int j = 0; j < 4; j++) acc[i][j] = 0.f;

    const int lrow = tid >> 2;       // 0..63
    const int lk   = (tid & 3) * 4;  // 0,4,8,12
    const int al   = tid & 63;
    const int ak   = (tid >> 6) * 4;

    const float* Abase = A;
    if (TRANSA) {
        int b = m0 / LLN;
        int l0 = m0 % LLN;
        Abase = A + (size_t)b * K * LLN + l0;
    }

    for (int k0 = 0; k0 < K; k0 += 16) {
        if (TRANSA) {
#pragma unroll
            for (int kk = 0; kk < 4; kk++)
                As[(ak + kk) * 64 + al] = Abase[(size_t)(k0 + ak + kk) * LLN + al];
        } else {
            float4 v = *(const float4*)(A + (size_t)(m0 + lrow) * K + k0 + lk);
            As[(lk + 0) * 64 + lrow] = v.x; As[(lk + 1) * 64 + lrow] = v.y;
            As[(lk + 2) * 64 + lrow] = v.z; As[(lk + 3) * 64 + lrow] = v.w;
        }
        {
            int n = n0 + lrow;
            float4 v = make_float4(0.f, 0.f, 0.f, 0.f);
            if (n < N) v = *(const float4*)(W + (size_t)n * K + k0 + lk);
            Bs[(lk + 0) * 64 + lrow] = v.x; Bs[(lk + 1) * 64 + lrow] = v.y;
            Bs[(lk + 2) * 64 + lrow] = v.z; Bs[(lk + 3) * 64 + lrow] = v.w;
        }
        __syncthreads();
#pragma unroll
        for (int kk = 0; kk < 16; kk++) {
            float a[4], b[4];
#pragma unroll
            for (int i = 0; i < 4; i++) a[i] = As[kk * 64 + ty + 16 * i];
#pragma unroll
            for (int j = 0; j < 4; j++) b[j] = Bs[kk * 64 + tx + 16 * j];
#pragma unroll
            for (int i = 0; i < 4; i++)
#pragma unroll
                for (int j = 0; j < 4; j++) acc[i][j] += a[i] * b[j];
        }
        __syncthreads();
    }

#pragma unroll
    for (int i = 0; i < 4; i++) {
        int m = m0 + ty + 16 * i;
#pragma unroll
        for (int j = 0; j < 4; j++) {
            int n = n0 + tx + 16 * j;
            if (n < N) {
                float v = acc[i][j];
                if (bias) v += bias[n];
                C[(size_t)m * N + n] = v;
            }
        }
    }
}

// ---------------- depthwise 3x3 conv + silu ----------------
// reads xin from g_xz[:, 0:384] (B,L,768 layout), writes g_xact (B,L,384)
__global__ void conv_silu_kernel(const float* __restrict__ conv_b)
{
    int gid = blockIdx.x * blockDim.x + threadIdx.x;   // M_TOT * 96
    int q = gid % 96;
    int m = gid / 96;
    int d = q * 4;
    int b = m / LLN, l = m % LLN;
    int h = l / HHN, w = l % HHN;

    float4 bias = *(const float4*)(conv_b + d);
    float a0 = bias.x, a1 = bias.y, a2 = bias.z, a3 = bias.w;

#pragma unroll
    for (int dy = -1; dy <= 1; dy++) {
        int hh = h + dy;
        if (hh < 0 || hh >= HHN) continue;
#pragma unroll
        for (int dx = -1; dx <= 1; dx++) {
            int ww = w + dx;
            if (ww < 0 || ww >= HHN) continue;
            int mm = b * LLN + hh * HHN + ww;
            float4 v  = *(const float4*)(g_xz + (size_t)mm * 768 + d);
            int j = (dy + 1) * 3 + (dx + 1);
            float4 wv = *(const float4*)(g_wT + j * DINNER + d);
            a0 += v.x * wv.x; a1 += v.y * wv.y; a2 += v.z * wv.z; a3 += v.w * wv.w;
        }
    }
    // silu
    a0 = a0 / (1.f + __expf(-a0));
    a1 = a1 / (1.f + __expf(-a1));
    a2 = a2 / (1.f + __expf(-a2));
    a3 = a3 / (1.f + __expf(-a3));
    *(float4*)(g_xact + (size_t)m * DINNER + d) = make_float4(a0, a1, a2, a3);
}

// ---------------- delta computation + packing ----------------
__global__ void delta_pack_kernel(const float* __restrict__ dt_proj_b)
{
    int m = blockIdx.x / 3;
    int dblk = blockIdx.x % 3;
    int tid = threadIdx.x;
    __shared__ float sxp[NXP];
    if (tid < NXP) sxp[tid] = g_xp[(size_t)m * NXP + tid];
    __syncthreads();

    int d = dblk * 128 + tid;
    float acc = dt_proj_b[d];
#pragma unroll
    for (int r = 0; r < DTRANK; r++)
        acc += sxp[r] * g_dtwT[r * DINNER + d];
    float delta = (acc > 20.f) ? acc : log1pf(__expf(acc));
    float u = g_xact[(size_t)m * DINNER + d];
    g_dd[(size_t)m * DINNER + d] = make_float2(delta, delta * u);

    if (dblk == 0 && tid < 8) {
        int sg = tid;
        g_bc[(size_t)m * 8 + sg] = make_float4(sxp[12 + 2 * sg], sxp[28 + 2 * sg],
                                               sxp[13 + 2 * sg], sxp[29 + 2 * sg]);
    }
}

// ---------------- selective scan ----------------
// warp: 4 channels x 8 state-groups (2 states/lane). grid 192 blocks x 128 thr.
__global__ void __launch_bounds__(128) scan_kernel(const float* __restrict__ A_log)
{
    int tid  = threadIdx.x;
    int warp = tid >> 5, lane = tid & 31;
    int c  = lane & 3;
    int sg = lane >> 2;            // 0..7
    int b  = blockIdx.x / 24;
    int d  = (blockIdx.x % 24) * 16 + warp * 4 + c;

    const float2* __restrict__ ddp = g_dd + (size_t)b * LLN * DINNER + d;
    const float4* __restrict__ bcp = g_bc + (size_t)b * LLN * 8 + sg;
    float* yp = g_y + (size_t)b * LLN * DINNER + d;

    float A0 = -expf(A_log[d * DSTATE + 2 * sg]);
    float A1 = -expf(A_log[d * DSTATE + 2 * sg + 1]);

    float h0 = 0.f, h1 = 0.f;
#pragma unroll 4
    for (int l = 0; l < LLN; l++) {
        float2 dv = ddp[(size_t)l * DINNER];
        float4 v  = bcp[(size_t)l * 8];
        float a0 = __expf(A0 * dv.x);
        float a1 = __expf(A1 * dv.x);
        h0 = a0 * h0 + dv.y * v.x;
        h1 = a1 * h1 + dv.y * v.z;
        float p = h0 * v.y + h1 * v.w;
        p += __shfl_xor_sync(0xffffffffu, p, 4);
        p += __shfl_xor_sync(0xffffffffu, p, 8);
        p += __shfl_xor_sync(0xffffffffu, p, 16);
        if (sg == 0) yp[(size_t)l * DINNER] = p;
    }
}

// ---------------- y + u*D -> LayerNorm -> * silu(z) ----------------
__global__ void __launch_bounds__(128) ln_gate_kernel(const float* __restrict__ D_param,
                                                      const float* __restrict__ ln_g,
                                                      const float* __restrict__ ln_b)
{
    int m = blockIdx.x;
    int tid = threadIdx.x;
    __shared__ float ws[4], wq[4], sstat[2];

    float t[3];
    float s = 0.f, sq = 0.f;
#pragma unroll
    for (int j = 0; j < 3; j++) {
        int d = tid + 128 * j;
        float v = g_y[(size_t)m * DINNER + d] + g_xact[(size_t)m * DINNER + d] * D_param[d];
        t[j] = v; s += v; sq += v * v;
    }
#pragma unroll
    for (int o = 16; o; o >>= 1) {
        s  += __shfl_xor_sync(0xffffffffu, s,  o);
        sq += __shfl_xor_sync(0xffffffffu, sq, o);
    }
    if ((tid & 31) == 0) { ws[tid >> 5] = s; wq[tid >> 5] = sq; }
    __syncthreads();
    if (tid == 0) {
        float S = ws[0] + ws[1] + ws[2] + ws[3];
        float Q = wq[0] + wq[1] + wq[2] + wq[3];
        float mu = S * (1.f / DINNER);
        float var = Q * (1.f / DINNER) - mu * mu;
        sstat[0] = mu;
        sstat[1] = rsqrtf(var + EPSF);
    }
    __syncthreads();
    float mu = sstat[0], rs = sstat[1];
#pragma unroll
    for (int j = 0; j < 3; j++) {
        int d = tid + 128 * j;
        float v = (t[j] - mu) * rs * ln_g[d] + ln_b[d];
        float z = g_xz[(size_t)m * 768 + DINNER + d];
        float sz = z / (1.f + __expf(-z));
        g_gate[(size_t)m * DINNER + d] = v * sz;
    }
}

// ---------------- instance-norm stats over L per (b,c) ----------------
__global__ void __launch_bounds__(256) in_stats_kernel()
{
    int bc = blockIdx.x;            // 0..1535
    int b = bc / DMODEL, c = bc % DMODEL;
    int tid = threadIdx.x;
    __shared__ float ws[8], wq[8], sstat[2];

    float s = 0.f, sq = 0.f;
    for (int l = tid; l < LLN; l += 256) {
        float v = g_fused[((size_t)b * LLN + l) * DMODEL + c];
        s += v; sq += v * v;
    }
#pragma unroll
    for (int o = 16; o; o >>= 1) {
        s  += __shfl_xor_sync(0xffffffffu, s,  o);
        sq += __shfl_xor_sync(0xffffffffu, sq, o);
    }
    if ((tid & 31) == 0) { ws[tid >> 5] = s; wq[tid >> 5] = sq; }
    __syncthreads();
    if (tid == 0) {
        float S = 0.f, Q = 0.f;
#pragma unroll
        for (int i = 0; i < 8; i++) { S += ws[i]; Q += wq[i]; }
        float mu = S * (1.f / LLN);
        float var = Q * (1.f / LLN) - mu * mu;
        g_stat[bc] = make_float2(mu, rsqrtf(var + EPSF));
    }
}

// ---------------- apply IN + residual, write NCHW output ----------------
__global__ void __launch_bounds__(256) in_apply_kernel(const float* __restrict__ x,
                                                       float* __restrict__ out)
{
    int gid = blockIdx.x * 256 + threadIdx.x;   // BATCHN*DMODEL*LLN
    int l = gid % LLN;
    int bc = gid / LLN;
    int b = bc / DMODEL, c = bc % DMODEL;
    float2 st = g_stat[bc];
    float v = g_fused[((size_t)b * LLN + l) * DMODEL + c];
    out[gid] = x[gid] + (v - st.x) * st.y;
}

// ---------------- launch ----------------
extern "C" void kernel_launch(void* const* d_in, const int* in_sizes, int n_in,
                              void* d_out, int out_size)
{
    const float* x          = (const float*)d_in[0];
    const float* in_proj_w  = (const float*)d_in[1];
    const float* conv_w     = (const float*)d_in[2];
    const float* conv_b     = (const float*)d_in[3];
    const float* x_proj_w   = (const float*)d_in[4];
    const float* dt_proj_w  = (const float*)d_in[5];
    const float* dt_proj_b  = (const float*)d_in[6];
    const float* A_log      = (const float*)d_in[7];
    const float* D_param    = (const float*)d_in[8];
    const float* ln_g       = (const float*)d_in[9];
    const float* ln_b       = (const float*)d_in[10];
    const float* out_proj_w = (const float*)d_in[11];
    const float* fuse_w     = (const float*)d_in[12];
    const float* fuse_b     = (const float*)d_in[13];
    float* out = (float*)d_out;

    float* xz;    cudaGetSymbolAddress((void**)&xz,    g_xz);
    float* xact;  cudaGetSymbolAddress((void**)&xact,  g_xact);
    float* xp;    cudaGetSymbolAddress((void**)&xp,    g_xp);
    float* gate;  cudaGetSymbolAddress((void**)&gate,  g_gate);
    float* fused; cudaGetSymbolAddress((void**)&fused, g_fused);
    float* Wc;    cudaGetSymbolAddress((void**)&Wc,    g_Wc);

    // 0. prep (Wc, weight transposes)
    prep_kernel<<<320, 256>>>(fuse_w, out_proj_w, dt_proj_w, conv_w);

    // 1. in_proj: xz[m][768] = x(NCHW) @ in_proj_w^T
    sgemm_kernel<1><<<dim3(768 / 64, M_TOT / 64), 256>>>(x, in_proj_w, nullptr, xz,
                                                         M_TOT, 768, DMODEL);
    // 2. depthwise conv 3x3 + silu
    conv_silu_kernel<<<(M_TOT * 96) / 256, 256>>>(conv_b);

    // 3. x_proj: xp[m][44] = xact @ x_proj_w^T
    sgemm_kernel<0><<<dim3(1, M_TOT / 64), 256>>>(xact, x_proj_w, nullptr, xp,
                                                  M_TOT, NXP, DINNER);
    // 4. delta + packing
    delta_pack_kernel<<<M_TOT * 3, 128>>>(dt_proj_b);

    // 5. selective scan
    scan_kernel<<<192, 128>>>(A_log);

    // 6. LN + gate
    ln_gate_kernel<<<M_TOT, 128>>>(D_param, ln_g, ln_b);

    // 7. combined out_proj + fuse 1x1: fused = gate @ Wc^T + fuse_b
    sgemm_kernel<0><<<dim3(DMODEL / 64, M_TOT / 64), 256>>>(gate, Wc, fuse_b, fused,
                                                            M_TOT, DMODEL, DINNER);
    // 8. instance norm stats
    in_stats_kernel<<<BATCHN * DMODEL, 256>>>();

    // 9. apply + residual
    in_apply_kernel<<<(BATCHN * DMODEL * LLN) / 256, 256>>>(x, out);
}

// round 2
// speedup vs baseline: 2.9587x; 2.9587x over previous
#include <cuda_runtime.h>
#include <cstdint>
#include <cstddef>

#define BATCHN 8
#define DMODEL 192
#define DINNER 384
#define DSTATE 16
#define DTRANK 12
#define HHN 48
#define LLN 2304            // 48*48
#define M_TOT (BATCHN*LLN)  // 18432
#define NXP 44              // DTRANK + 2*DSTATE
#define EPSF 1e-5f
#define NCHUNK 8
#define CLEN (LLN/NCHUNK)   // 288

// ---------------- scratch (no allocations allowed) ----------------
__device__ float  g_xz   [(size_t)M_TOT*768];     // in_proj output: [m][768] (xin | z)
__device__ float  g_xact [(size_t)M_TOT*DINNER];  // conv+silu output (B,L,D)
__device__ float  g_xp   [(size_t)M_TOT*NXP];     // x_proj output
__device__ float2 g_dd   [(size_t)M_TOT*DINNER];  // (delta, delta*u)
__device__ float4 g_bc   [(size_t)M_TOT*8];       // (B[2s],C[2s],B[2s+1],C[2s+1])
__device__ float  g_y    [(size_t)M_TOT*DINNER];  // scan output (without u*D)
__device__ float  g_gate [(size_t)M_TOT*DINNER];  // LN * silu(z)
__device__ float  g_fused[(size_t)M_TOT*DMODEL];  // out_proj+fuse GEMM, NCL layout [b][c][l]
__device__ float  g_Wc   [DMODEL*DINNER];         // fuse_w @ out_proj_w
__device__ float  g_dtwT [DTRANK*DINNER];         // dt_proj_w transposed [r][d]
__device__ float  g_wT   [9*DINNER];              // conv_w transposed [j][d]
__device__ float2 g_stat [BATCHN*DMODEL];         // instance-norm (mean, rstd)
__device__ float4 g_carry[BATCHN*NCHUNK*DINNER*8]; // (P0,S0,P1,S1) per (b,chunk,d,sg)
__device__ float2 g_cin  [BATCHN*NCHUNK*DINNER*8]; // carry-in h per (b,chunk,d,sg)

// ---------------- prep: Wc = fuse_w @ out_proj_w ; transposes ----------------
__global__ void prep_kernel(const float* __restrict__ fuse_w,
                            const float* __restrict__ out_proj_w,
                            const float* __restrict__ dt_proj_w,
                            const float* __restrict__ conv_w)
{
    int gid = blockIdx.x * blockDim.x + threadIdx.x;
    if (gid < DMODEL * DINNER) {
        int c = gid / DINNER, d = gid % DINNER;
        float s = 0.f;
        for (int o = 0; o < DMODEL; o++)
            s += fuse_w[c * DMODEL + o] * out_proj_w[(size_t)o * DINNER + d];
        g_Wc[gid] = s;
    } else if (gid < DMODEL * DINNER + DTRANK * DINNER) {
        int t = gid - DMODEL * DINNER;
        int r = t / DINNER, d = t % DINNER;
        g_dtwT[t] = dt_proj_w[d * DTRANK + r];
    } else if (gid < DMODEL * DINNER + DTRANK * DINNER + 9 * DINNER) {
        int t = gid - DMODEL * DINNER - DTRANK * DINNER;
        int j = t / DINNER, d = t % DINNER;
        g_wT[t] = conv_w[d * 9 + j];
    }
}

// ---------------- 128x64 SGEMM, 8x4 microtile, reg-prefetch double buffer ----
// C[m][n] = sum_k A(m,k) * W[n][k]  (+bias[n])
// TRANSA=0: A row-major [M,K].  TRANSA=1: A(m,k) = A[(b*K+k)*LLN + l], m=b*LLN+l.
// TRANSC=0: C row-major [M,N].  TRANSC=1: C[(b*N+n)*LLN + l] (NCL).
template<int TRANSA, int TRANSC>
__global__ void __launch_bounds__(256) sgemm2_kernel(
    const float* __restrict__ A, const float* __restrict__ W,
    const float* __restrict__ bias, float* __restrict__ C,
    int M, int N, int K)
{
    __shared__ float As[16][128];
    __shared__ float Bs[16][64];
    const int tid = threadIdx.x;
    const int m0 = blockIdx.y * 128;
    const int n0 = blockIdx.x * 64;
    const int ty4 = (tid >> 4) * 4;   // 0..60
    const int tx4 = (tid & 15) * 4;   // 0..60

    // A-load indexing
    const int am  = tid >> 1;          // TRANSA=0: row within tile (0..127)
    const int ak  = (tid & 1) * 8;     // TRANSA=0: k offset (0 or 8)
    const int ak1 = tid >> 4;          // TRANSA=1: k row (0..15)
    const int al  = (tid & 15) * 8;    // TRANSA=1: l offset (0..120)
    // B-load indexing
    const int bn = tid >> 2;           // 0..63
    const int bk = (tid & 3) * 4;      // 0,4,8,12

    const float* Aptr;
    if (TRANSA) {
        int b = m0 / LLN, l0 = m0 % LLN;
        Aptr = A + ((size_t)b * K + ak1) * LLN + l0 + al;
    } else {
        Aptr = A + (size_t)(m0 + am) * K + ak;
    }
    const bool bvalid = (n0 + bn) < N;
    const float* Bptr = W + (size_t)(n0 + bn) * K + bk;

    float ra[8], rb[4];
    float acc[8][4];
#pragma unroll
    for (int i = 0; i < 8; i++)
#pragma unroll
        for (int j = 0; j < 4; j++) acc[i][j] = 0.f;

    const int ntiles = K >> 4;

    // load tile 0
    {
        const float* p = TRANSA ? Aptr : Aptr;
        float4 u0, u1;
        if (TRANSA) { u0 = *(const float4*)(p); u1 = *(const float4*)(p + 4); }
        else        { u0 = *(const float4*)(p); u1 = *(const float4*)(p + 4); }
        ra[0]=u0.x; ra[1]=u0.y; ra[2]=u0.z; ra[3]=u0.w;
        ra[4]=u1.x; ra[5]=u1.y; ra[6]=u1.z; ra[7]=u1.w;
        float4 v = make_float4(0.f,0.f,0.f,0.f);
        if (bvalid) v = *(const float4*)(Bptr);
        rb[0]=v.x; rb[1]=v.y; rb[2]=v.z; rb[3]=v.w;
    }
    // store tile 0
    if (TRANSA) {
        *(float4*)&As[ak1][al]     = make_float4(ra[0],ra[1],ra[2],ra[3]);
        *(float4*)&As[ak1][al + 4] = make_float4(ra[4],ra[5],ra[6],ra[7]);
    } else {
#pragma unroll
        for (int c = 0; c < 8; c++) As[ak + c][am] = ra[c];
    }
#pragma unroll
    for (int c = 0; c < 4; c++) Bs[bk + c][bn] = rb[c];
    __syncthreads();

    for (int t = 0; t < ntiles; t++) {
        if (t + 1 < ntiles) {
            if (TRANSA) {
                const float* p = Aptr + (size_t)(t + 1) * 16 * LLN;
                float4 u0 = *(const float4*)(p);
                float4 u1 = *(const float4*)(p + 4);
                ra[0]=u0.x; ra[1]=u0.y; ra[2]=u0.z; ra[3]=u0.w;
                ra[4]=u1.x; ra[5]=u1.y; ra[6]=u1.z; ra[7]=u1.w;
            } else {
                const float* p = Aptr + (t + 1) * 16;
                float4 u0 = *(const float4*)(p);
                float4 u1 = *(const float4*)(p + 4);
                ra[0]=u0.x; ra[1]=u0.y; ra[2]=u0.z; ra[3]=u0.w;
                ra[4]=u1.x; ra[5]=u1.y; ra[6]=u1.z; ra[7]=u1.w;
            }
            float4 v = make_float4(0.f,0.f,0.f,0.f);
            if (bvalid) v = *(const float4*)(Bptr + (t + 1) * 16);
            rb[0]=v.x; rb[1]=v.y; rb[2]=v.z; rb[3]=v.w;
        }
#pragma unroll
        for (int kk = 0; kk < 16; kk++) {
            float4 a0 = *(const float4*)&As[kk][ty4];
            float4 a1 = *(const float4*)&As[kk][ty4 + 64];
            float4 b  = *(const float4*)&Bs[kk][tx4];
            float av[8] = {a0.x,a0.y,a0.z,a0.w,a1.x,a1.y,a1.z,a1.w};
            float bv[4] = {b.x,b.y,b.z,b.w};
#pragma unroll
            for (int i = 0; i < 8; i++)
#pragma unroll
                for (int j = 0; j < 4; j++) acc[i][j] += av[i] * bv[j];
        }
        __syncthreads();
        if (t + 1 < ntiles) {
            if (TRANSA) {
                *(float4*)&As[ak1][al]     = make_float4(ra[0],ra[1],ra[2],ra[3]);
                *(float4*)&As[ak1][al + 4] = make_float4(ra[4],ra[5],ra[6],ra[7]);
            } else {
#pragma unroll
                for (int c = 0; c < 8; c++) As[ak + c][am] = ra[c];
            }
#pragma unroll
            for (int c = 0; c < 4; c++) Bs[bk + c][bn] = rb[c];
            __syncthreads();
        }
    }

    if (TRANSC) {
        // C[(b*N+n)*LLN + l], bias added; N assumed multiple of 4 here
        int b = m0 / LLN, l0 = m0 % LLN;
#pragma unroll
        for (int j = 0; j < 4; j++) {
            int n = n0 + tx4 + j;
            float bv = bias ? bias[n] : 0.f;
            float* cp = C + ((size_t)b * N + n) * LLN + l0;
            *(float4*)(cp + ty4)      = make_float4(acc[0][j]+bv, acc[1][j]+bv,
                                                    acc[2][j]+bv, acc[3][j]+bv);
            *(float4*)(cp + ty4 + 64) = make_float4(acc[4][j]+bv, acc[5][j]+bv,
                                                    acc[6][j]+bv, acc[7][j]+bv);
        }
    } else {
#pragma unroll
        for (int i = 0; i < 8; i++) {
            int m = m0 + ty4 % 4 + (ty4 / 4) * 4 + ((i < 4) ? i - (ty4 % 4) : 0); // unused form
            (void)m;
        }
#pragma unroll
        for (int i = 0; i < 8; i++) {
            int mm = m0 + ((i < 4) ? (ty4 + i) : (ty4 + 64 + i - 4));
            if (n0 + tx4 + 4 <= N) {
                float b0 = bias ? bias[n0+tx4+0] : 0.f;
                float b1 = bias ? bias[n0+tx4+1] : 0.f;
                float b2 = bias ? bias[n0+tx4+2] : 0.f;
                float b3 = bias ? bias[n0+tx4+3] : 0.f;
                *(float4*)(C + (size_t)mm * N + n0 + tx4) =
                    make_float4(acc[i][0]+b0, acc[i][1]+b1, acc[i][2]+b2, acc[i][3]+b3);
            } else {
#pragma unroll
                for (int j = 0; j < 4; j++) {
                    int n = n0 + tx4 + j;
                    if (n < N) {
                        float bv = bias ? bias[n] : 0.f;
                        C[(size_t)mm * N + n] = acc[i][j] + bv;
                    }
                }
            }
        }
    }
}

// ---------------- depthwise 3x3 conv + silu ----------------
__global__ void conv_silu_kernel(const float* __restrict__ conv_b)
{
    int gid = blockIdx.x * blockDim.x + threadIdx.x;   // M_TOT * 96
    int q = gid % 96;
    int m = gid / 96;
    int d = q * 4;
    int b = m / LLN, l = m % LLN;
    int h = l / HHN, w = l % HHN;

    float4 bias = *(const float4*)(conv_b + d);
    float a0 = bias.x, a1 = bias.y, a2 = bias.z, a3 = bias.w;

#pragma unroll
    for (int dy = -1; dy <= 1; dy++) {
        int hh = h + dy;
        if (hh < 0 || hh >= HHN) continue;
#pragma unroll
        for (int dx = -1; dx <= 1; dx++) {
            int ww = w + dx;
            if (ww < 0 || ww >= HHN) continue;
            int mm = b * LLN + hh * HHN + ww;
            float4 v  = *(const float4*)(g_xz + (size_t)mm * 768 + d);
            int j = (dy + 1) * 3 + (dx + 1);
            float4 wv = *(const float4*)(g_wT + j * DINNER + d);
            a0 += v.x * wv.x; a1 += v.y * wv.y; a2 += v.z * wv.z; a3 += v.w * wv.w;
        }
    }
    a0 = a0 / (1.f + __expf(-a0));
    a1 = a1 / (1.f + __expf(-a1));
    a2 = a2 / (1.f + __expf(-a2));
    a3 = a3 / (1.f + __expf(-a3));
    *(float4*)(g_xact + (size_t)m * DINNER + d) = make_float4(a0, a1, a2, a3);
}

// ---------------- delta computation + packing ----------------
__global__ void delta_pack_kernel(const float* __restrict__ dt_proj_b)
{
    int m = blockIdx.x / 3;
    int dblk = blockIdx.x % 3;
    int tid = threadIdx.x;
    __shared__ float sxp[NXP];
    if (tid < NXP) sxp[tid] = g_xp[(size_t)m * NXP + tid];
    __syncthreads();

    int d = dblk * 128 + tid;
    float acc = dt_proj_b[d];
#pragma unroll
    for (int r = 0; r < DTRANK; r++)
        acc += sxp[r] * g_dtwT[r * DINNER + d];
    float delta = (acc > 20.f) ? acc : log1pf(__expf(acc));
    float u = g_xact[(size_t)m * DINNER + d];
    g_dd[(size_t)m * DINNER + d] = make_float2(delta, delta * u);

    if (dblk == 0 && tid < 8) {
        int sg = tid;
        g_bc[(size_t)m * 8 + sg] = make_float4(sxp[12 + 2 * sg], sxp[28 + 2 * sg],
                                               sxp[13 + 2 * sg], sxp[29 + 2 * sg]);
    }
}

// ---------------- scan pass 1: per-chunk (P, S) carries ----------------
// block: 4 warps, warp = 4 channels x 8 sg (2 states per lane)
// grid: b(8) x chunk(8) x dgroup(24) = 1536 blocks
__global__ void __launch_bounds__(128) scan_carry_kernel(const float* __restrict__ A_log)
{
    int tid  = threadIdx.x;
    int warp = tid >> 5, lane = tid & 31;
    int c  = lane & 3;
    int sg = lane >> 2;
    int blk = blockIdx.x;
    int b     = blk / (NCHUNK * 24);
    int chunk = (blk / 24) % NCHUNK;
    int dg    = blk % 24;
    int d  = dg * 16 + warp * 4 + c;
    int l0 = chunk * CLEN;

    const float2* __restrict__ ddp = g_dd + ((size_t)b * LLN + l0) * DINNER + d;
    const float4* __restrict__ bcp = g_bc + ((size_t)b * LLN + l0) * 8 + sg;

    float A0 = -expf(A_log[d * DSTATE + 2 * sg]);
    float A1 = -expf(A_log[d * DSTATE + 2 * sg + 1]);

    float h0 = 0.f, h1 = 0.f, p0 = 1.f, p1 = 1.f;
#pragma unroll 4
    for (int l = 0; l < CLEN; l++) {
        float2 dv = ddp[(size_t)l * DINNER];
        float4 v  = bcp[(size_t)l * 8];
        float a0 = __expf(A0 * dv.x);
        float a1 = __expf(A1 * dv.x);
        h0 = a0 * h0 + dv.y * v.x;  p0 *= a0;
        h1 = a1 * h1 + dv.y * v.z;  p1 *= a1;
    }
    g_carry[(((size_t)b * NCHUNK + chunk) * DINNER + d) * 8 + sg] =
        make_float4(p0, h0, p1, h1);
}

// ---------------- scan pass 2: chunk-level sequential combine ----------------
__global__ void __launch_bounds__(256) scan_combine_kernel()
{
    int gid = blockIdx.x * 256 + threadIdx.x;   // B * DINNER * 8 = 24576
    int b = gid / (DINNER * 8);
    int r = gid % (DINNER * 8);
    float h0 = 0.f, h1 = 0.f;
#pragma unroll
    for (int j = 0; j < NCHUNK; j++) {
        size_t idx = ((size_t)(b * NCHUNK + j) * DINNER) * 8 + r;
        g_cin[idx] = make_float2(h0, h1);
        float4 cr = g_carry[idx];
        h0 = cr.x * h0 + cr.y;
        h1 = cr.z * h1 + cr.w;
    }
}

// ---------------- scan pass 3: full scan with carry-in, write y ----------------
__global__ void __launch_bounds__(128) scan_final_kernel(const float* __restrict__ A_log)
{
    int tid  = threadIdx.x;
    int warp = tid >> 5, lane = tid & 31;
    int c  = lane & 3;
    int sg = lane >> 2;
    int blk = blockIdx.x;
    int b     = blk / (NCHUNK * 24);
    int chunk = (blk / 24) % NCHUNK;
    int dg    = blk % 24;
    int d  = dg * 16 + warp * 4 + c;
    int l0 = chunk * CLEN;

    const float2* __restrict__ ddp = g_dd + ((size_t)b * LLN + l0) * DINNER + d;
    const float4* __restrict__ bcp = g_bc + ((size_t)b * LLN + l0) * 8 + sg;
    float* yp = g_y + ((size_t)b * LLN + l0) * DINNER + d;

    float A0 = -expf(A_log[d * DSTATE + 2 * sg]);
    float A1 = -expf(A_log[d * DSTATE + 2 * sg + 1]);

    float2 ci = g_cin[(((size_t)b * NCHUNK + chunk) * DINNER + d) * 8 + sg];
    float h0 = ci.x, h1 = ci.y;
#pragma unroll 4
    for (int l = 0; l < CLEN; l++) {
        float2 dv = ddp[(size_t)l * DINNER];
        float4 v  = bcp[(size_t)l * 8];
        float a0 = __expf(A0 * dv.x);
        float a1 = __expf(A1 * dv.x);
        h0 = a0 * h0 + dv.y * v.x;
        h1 = a1 * h1 + dv.y * v.z;
        float p = h0 * v.y + h1 * v.w;
        p += __shfl_xor_sync(0xffffffffu, p, 4);
        p += __shfl_xor_sync(0xffffffffu, p, 8);
        p += __shfl_xor_sync(0xffffffffu, p, 16);
        if (sg == 0) yp[(size_t)l * DINNER] = p;
    }
}

// ---------------- y + u*D -> LayerNorm -> * silu(z)  (warp per row) ----------
__global__ void __launch_bounds__(128) ln_gate_kernel(const float* __restrict__ D_param,
                                                      const float* __restrict__ ln_g,
                                                      const float* __restrict__ ln_b)
{
    int warp = threadIdx.x >> 5;
    int lane = threadIdx.x & 31;
    int m = blockIdx.x * 4 + warp;

    float t[12];
    float s = 0.f, sq = 0.f;
#pragma unroll
    for (int j = 0; j < 12; j++) {
        int d = j * 32 + lane;
        float v = g_y[(size_t)m * DINNER + d] + g_xact[(size_t)m * DINNER + d] * D_param[d];
        t[j] = v; s += v; sq += v * v;
    }
#pragma unroll
    for (int o = 16; o; o >>= 1) {
        s  += __shfl_xor_sync(0xffffffffu, s,  o);
        sq += __shfl_xor_sync(0xffffffffu, sq, o);
    }
    float mu = s * (1.f / DINNER);
    float var = sq * (1.f / DINNER) - mu * mu;
    float rs = rsqrtf(var + EPSF);
#pragma unroll
    for (int j = 0; j < 12; j++) {
        int d = j * 32 + lane;
        float v = (t[j] - mu) * rs * ln_g[d] + ln_b[d];
        float z = g_xz[(size_t)m * 768 + DINNER + d];
        float sz = z / (1.f + __expf(-z));
        g_gate[(size_t)m * DINNER + d] = v * sz;
    }
}

// ---------------- instance-norm stats over L per (b,c); NCL layout ----------
__global__ void __launch_bounds__(256) in_stats_kernel()
{
    int bc = blockIdx.x;            // 0..1535
    int tid = threadIdx.x;
    __shared__ float ws[8], wq[8];

    const float* p = g_fused + (size_t)bc * LLN;
    float s = 0.f, sq = 0.f;
#pragma unroll
    for (int i = 0; i < LLN / 256; i++) {
        float v = p[tid + i * 256];
        s += v; sq += v * v;
    }
#pragma unroll
    for (int o = 16; o; o >>= 1) {
        s  += __shfl_xor_sync(0xffffffffu, s,  o);
        sq += __shfl_xor_sync(0xffffffffu, sq, o);
    }
    if ((tid & 31) == 0) { ws[tid >> 5] = s; wq[tid >> 5] = sq; }
    __syncthreads();
    if (tid == 0) {
        float S = 0.f, Q = 0.f;
#pragma unroll
        for (int i = 0; i < 8; i++) { S += ws[i]; Q += wq[i]; }
        float mu = S * (1.f / LLN);
        float var = Q * (1.f / LLN) - mu * mu;
        g_stat[bc] = make_float2(mu, rsqrtf(var + EPSF));
    }
}

// ---------------- apply IN + residual, write NCHW output ----------------
__global__ void __launch_bounds__(256) in_apply_kernel(const float* __restrict__ x,
                                                       float* __restrict__ out)
{
    int gid = blockIdx.x * 256 + threadIdx.x;   // BATCHN*DMODEL*LLN
    int bc = gid / LLN;
    float2 st = g_stat[bc];
    float v = g_fused[gid];
    out[gid] = x[gid] + (v - st.x) * st.y;
}

// ---------------- launch ----------------
extern "C" void kernel_launch(void* const* d_in, const int* in_sizes, int n_in,
                              void* d_out, int out_size)
{
    const float* x          = (const float*)d_in[0];
    const float* in_proj_w  = (const float*)d_in[1];
    const float* conv_w     = (const float*)d_in[2];
    const float* conv_b     = (const float*)d_in[3];
    const float* x_proj_w   = (const float*)d_in[4];
    const float* dt_proj_w  = (const float*)d_in[5];
    const float* dt_proj_b  = (const float*)d_in[6];
    const float* A_log      = (const float*)d_in[7];
    const float* D_param    = (const float*)d_in[8];
    const float* ln_g       = (const float*)d_in[9];
    const float* ln_b       = (const float*)d_in[10];
    const float* out_proj_w = (const float*)d_in[11];
    const float* fuse_w     = (const float*)d_in[12];
    const float* fuse_b     = (const float*)d_in[13];
    float* out = (float*)d_out;

    float* xz;    cudaGetSymbolAddress((void**)&xz,    g_xz);
    float* xact;  cudaGetSymbolAddress((void**)&xact,  g_xact);
    float* xp;    cudaGetSymbolAddress((void**)&xp,    g_xp);
    float* gate;  cudaGetSymbolAddress((void**)&gate,  g_gate);
    float* fused; cudaGetSymbolAddress((void**)&fused, g_fused);
    float* Wc;    cudaGetSymbolAddress((void**)&Wc,    g_Wc);

    // 0. prep (Wc, weight transposes)
    prep_kernel<<<320, 256>>>(fuse_w, out_proj_w, dt_proj_w, conv_w);

    // 1. in_proj: xz[m][768] = x(NCHW) @ in_proj_w^T
    sgemm2_kernel<1, 0><<<dim3(768 / 64, M_TOT / 128), 256>>>(
        x, in_proj_w, nullptr, xz, M_TOT, 768, DMODEL);

    // 2. depthwise conv 3x3 + silu
    conv_silu_kernel<<<(M_TOT * 96) / 256, 256>>>(conv_b);

    // 3. x_proj: xp[m][44] = xact @ x_proj_w^T
    sgemm2_kernel<0, 0><<<dim3(1, M_TOT / 128), 256>>>(
        xact, x_proj_w, nullptr, xp, M_TOT, NXP, DINNER);

    // 4. delta + packing
    delta_pack_kernel<<<M_TOT * 3, 128>>>(dt_proj_b);

    // 5. selective scan (chunked, 3 passes)
    scan_carry_kernel<<<BATCHN * NCHUNK * 24, 128>>>(A_log);
    scan_combine_kernel<<<(BATCHN * DINNER * 8) / 256, 256>>>();
    scan_final_kernel<<<BATCHN * NCHUNK * 24, 128>>>(A_log);

    // 6. LN + gate (warp per row)
    ln_gate_kernel<<<M_TOT / 4, 128>>>(D_param, ln_g, ln_b);

    // 7. combined out_proj + fuse 1x1: fused(NCL) = gate @ Wc^T + fuse_b
    sgemm2_kernel<0, 1><<<dim3(DMODEL / 64, M_TOT / 128), 256>>>(
        gate, Wc, fuse_b, fused, M_TOT, DMODEL, DINNER);

    // 8. instance norm stats (coalesced over L)
    in_stats_kernel<<<BATCHN * DMODEL, 256>>>();

    // 9. apply + residual (fully coalesced)
    in_apply_kernel<<<(BATCHN * DMODEL * LLN) / 256, 256>>>(x, out);
}